// round 9
// baseline (speedup 1.0000x reference)
#include <cuda_runtime.h>
#include <math.h>

#define FRAME_SIZE 160
#define LPC_N 16
#define T_LEN 2400
#define T4 (T_LEN / 4)                 // 600 float4 per row
#define N_FRAMES 15
#define B_SZ 1024

#define NTHREADS 640                   // 600 work threads + 4 pad writers
#define NWORK T4                       // 600 threads, 4 samples each

#define SCALE    (255.0f / 32768.0f)
#define SCALE_1  (32768.0f / 255.0f)

__device__ __forceinline__ float ex2_approx(float x) {
    float y; asm("ex2.approx.f32 %0, %1;" : "=f"(y) : "f"(x)); return y;
}
__device__ __forceinline__ float lg2_approx(float x) {
    float y; asm("lg2.approx.f32 %0, %1;" : "=f"(y) : "f"(x)); return y;
}

// mu-law (0..255) -> linear.  exp(u/128*ln256) == 2^(u/16)
__device__ __forceinline__ float u2l(float v) {
    float u = v - 128.0f;
    float m = fmaf(SCALE_1, ex2_approx(fabsf(u) * 0.0625f), -SCALE_1);
    return copysignf(m, u);
}
// l2u(-a) = clip(128 - copysign(16*log2(1 + SCALE*|a|), a), 0, 255)
__device__ __forceinline__ float l2u_neg(float a) {
    float u = lg2_approx(fmaf(SCALE, fabsf(a), 1.0f));
    float s = copysignf(16.0f, a);
    return fminf(fmaxf(fmaf(-s, u, 128.0f), 0.0f), 255.0f);
}

__device__ __forceinline__ float4 dec4(float4 v) {
    float4 d;
    d.x = u2l(v.x); d.y = u2l(v.y); d.z = u2l(v.z); d.w = u2l(v.w);
    return d;
}

// One block per batch row. 640 threads:
//   threads 0..599  : decode one float4 group into shared; then FIR 4 samples
//   threads 600..603: write the 16-sample zero history pad
// No halo loads, no chunk branches — the whole row's history is zero.
__global__ __launch_bounds__(NTHREADS)
void diff_pred_kernel(const float4* __restrict__ sig,
                      const float*  __restrict__ lpc,
                      float4* __restrict__ out) {
    __shared__ __align__(16) float sx[LPC_N + T_LEN];   // zero pad + decoded row
    float4* sx4 = (float4*)sx;

    const int b   = blockIdx.x;
    const int tid = threadIdx.x;

    // ---- front-batch all global loads (sig group + this thread's coeffs) ----
    float4 c0, c1, c2, c3;
    if (tid < NWORK) {
        float4 v = sig[b * T4 + tid];
        // frame of this thread's 4 samples: 4*tid/160 = tid/40
        const int f = tid / (FRAME_SIZE / 4);
        const float4* lrow = (const float4*)(lpc + (size_t)b * (N_FRAMES * LPC_N)
                                             + f * LPC_N);
        c0 = lrow[0]; c1 = lrow[1]; c2 = lrow[2]; c3 = lrow[3];
        sx4[4 + tid] = dec4(v);
    } else if (tid < NWORK + 4) {
        sx4[tid - NWORK] = make_float4(0.f, 0.f, 0.f, 0.f);   // zero history
    }
    __syncthreads();

    if (tid >= NWORK) return;

    // 20-sample window sx[4*tid .. 4*tid+19] (5 LDS.128, front-batched)
    float x[20];
#pragma unroll
    for (int k = 0; k < 5; ++k) {
        float4 xx = sx4[tid + k];
        x[4 * k] = xx.x; x[4 * k + 1] = xx.y; x[4 * k + 2] = xx.z; x[4 * k + 3] = xx.w;
    }

    const float c[LPC_N] = { c0.x, c0.y, c0.z, c0.w, c1.x, c1.y, c1.z, c1.w,
                             c2.x, c2.y, c2.z, c2.w, c3.x, c3.y, c3.z, c3.w };

    // output sample 4*tid + j uses x[16 + j - i], i = 0..15
    float a0 = 0.f, a1 = 0.f, a2 = 0.f, a3 = 0.f;
#pragma unroll
    for (int i = 0; i < LPC_N; ++i) {
        a0 = fmaf(c[i], x[16 - i], a0);
        a1 = fmaf(c[i], x[17 - i], a1);
        a2 = fmaf(c[i], x[18 - i], a2);
        a3 = fmaf(c[i], x[19 - i], a3);
    }

    float4 r;
    r.x = l2u_neg(a0); r.y = l2u_neg(a1); r.z = l2u_neg(a2); r.w = l2u_neg(a3);
    out[b * T4 + tid] = r;
}

extern "C" void kernel_launch(void* const* d_in, const int* in_sizes, int n_in,
                              void* d_out, int out_size) {
    const float4* sig = (const float4*)d_in[0];  // (B, 2400, 1) f32
    const float*  lpc = (const float*)d_in[1];   // (B, 15, 16) f32
    float4* out = (float4*)d_out;                // (B, 2400, 1) f32

    diff_pred_kernel<<<B_SZ, NTHREADS>>>(sig, lpc, out);
}